// round 4
// baseline (speedup 1.0000x reference)
#include <cuda_runtime.h>
#include <cstdint>
#include <cstddef>

// Problem: X [8,256,64,64]; three 3x3 SAME convs 256->256; spatial attention.
#define BB   8
#define CC   256
#define HH   64
#define WW   64
#define NN   4096

// ---------------- scratch (static __device__ arrays; no allocation) ----------
__device__ float g_A[BB * CC * NN];          // conv1 out [b][c][n]
__device__ float g_B[BB * CC * NN];          // conv2 out
__device__ float g_D[BB * CC * NN];          // conv3 out
__device__ float g_M[134217728];             // attention logits/probs [b][n][m]
__device__ float g_Wt[3 * 9 * 256 * 256];    // weights as [which][tap][ci][co]

// ---------------- kernel 0: weight transpose --------------------------------
// w: [co][ci][ky][kx] (OIHW) -> Wt: [tap][ci][co] (co contiguous)
__global__ void wtrans_kernel(const float* __restrict__ w1,
                              const float* __restrict__ w2,
                              const float* __restrict__ w3) {
    int idx = blockIdx.x * 256 + threadIdx.x;
    int which = idx / 589824;
    int r     = idx % 589824;
    int tap   = r / 65536;
    int rem   = r % 65536;
    int ci    = rem / 256;
    int co    = rem % 256;
    const float* w = (which == 0) ? w1 : (which == 1) ? w2 : w3;
    g_Wt[which * 589824 + (tap * 256 + ci) * 256 + co] =
        w[(co * 256 + ci) * 9 + tap];
}

// ---------------- kernel 1: 3x3 conv as 9 shifted GEMM taps ------------------
// Output tile: 128 co x 128 pixels (2 image rows). BK=8 over ci, 8x8 microtile.
// grid (32 n-tiles, 2 co-tiles, 8 batch), 256 threads.
__global__ void __launch_bounds__(256, 2)
conv3x3_kernel(const float* __restrict__ X,
               const float* __restrict__ bias,
               int which) {
    const float* Wt = g_Wt + (size_t)which * 589824;
    float* Y = (which == 0) ? g_A : (which == 1) ? g_B : g_D;

    int y0  = blockIdx.x * 2;          // first image row of this pixel tile
    int n0  = y0 * WW;                 // 128-pixel tile base
    int co0 = blockIdx.y * 128;
    int b   = blockIdx.z;

    __shared__ float Ws[8][132];       // [ci_l][co_l]
    __shared__ float Xs[8][132];       // [ci_l][pix_l]

    int tid = threadIdx.x;
    int tx = tid & 15, ty = tid >> 4;  // 16x16 logical; 8x8 microtile

    float acc[8][8] = {};
    const float* Xb = X + (size_t)b * CC * NN;

    // Ws float4 load coords (per phase)
    int wr  = tid >> 5;                // 0..7 (ci_l)
    int wc4 = (tid & 31) * 4;          // 0..124

    for (int tap = 0; tap < 9; ++tap) {
        int dy = tap / 3 - 1, dx = tap % 3 - 1;
        const float* Wtap = Wt + tap * 65536;

        for (int ck = 0; ck < CC; ck += 8) {
            // load weights: 8 x 128, coalesced float4
            {
                float4 wv = *(const float4*)&Wtap[(ck + wr) * 256 + co0 + wc4];
                Ws[wr][wc4 + 0] = wv.x;
                Ws[wr][wc4 + 1] = wv.y;
                Ws[wr][wc4 + 2] = wv.z;
                Ws[wr][wc4 + 3] = wv.w;
            }
            // load shifted input pixels: 8 x 128, scalar (dx-shift breaks alignment)
            #pragma unroll
            for (int i = 0; i < 4; ++i) {
                int idx = tid + i * 256;
                int r = idx >> 7;          // ci_l
                int p = idx & 127;         // pixel in tile
                int py = y0 + (p >> 6) + dy;
                int px = (p & 63) + dx;
                float v = 0.0f;
                if (py >= 0 && py < HH && px >= 0 && px < WW)
                    v = Xb[(size_t)(ck + r) * NN + py * WW + px];
                Xs[r][p] = v;
            }
            __syncthreads();
            #pragma unroll
            for (int k = 0; k < 8; ++k) {
                float a[8], x[8];
                *(float4*)&a[0] = *(const float4*)&Ws[k][8 * ty];
                *(float4*)&a[4] = *(const float4*)&Ws[k][8 * ty + 4];
                *(float4*)&x[0] = *(const float4*)&Xs[k][8 * tx];
                *(float4*)&x[4] = *(const float4*)&Xs[k][8 * tx + 4];
                #pragma unroll
                for (int i = 0; i < 8; ++i)
                    #pragma unroll
                    for (int j = 0; j < 8; ++j)
                        acc[i][j] = fmaf(a[i], x[j], acc[i][j]);
            }
            __syncthreads();
        }
    }

    #pragma unroll
    for (int i = 0; i < 8; ++i) {
        int co = co0 + 8 * ty + i;
        float bz = bias[co];
        float* dst = Y + ((size_t)b * CC + co) * NN + n0 + 8 * tx;
        float4 v0 = make_float4(acc[i][0] + bz, acc[i][1] + bz,
                                acc[i][2] + bz, acc[i][3] + bz);
        float4 v1 = make_float4(acc[i][4] + bz, acc[i][5] + bz,
                                acc[i][6] + bz, acc[i][7] + bz);
        *(float4*)dst       = v0;
        *(float4*)(dst + 4) = v1;
    }
}

// ---------------- kernel 2: S[b][n][m] = sum_c A[b][c][n]*B[b][c][m] ---------
// 128x128 tile, BK=8, 8x8 microtile. grid (32 m, 32 n, 8 b).
__global__ void __launch_bounds__(256, 2)
gemm_s_kernel() {
    int b  = blockIdx.z;
    int n0 = blockIdx.y * 128;
    int m0 = blockIdx.x * 128;

    __shared__ float As[8][132];   // [c_l][n_l]
    __shared__ float Bs[8][132];   // [c_l][m_l]

    int tid = threadIdx.x;
    int tx = tid & 15, ty = tid >> 4;
    int lr  = tid >> 5;            // 0..7
    int lc4 = (tid & 31) * 4;      // 0..124

    const float* Ab = g_A + (size_t)b * CC * NN;
    const float* Bp = g_B + (size_t)b * CC * NN;

    float acc[8][8] = {};
    for (int ck = 0; ck < CC; ck += 8) {
        float4 av = *(const float4*)&Ab[(size_t)(ck + lr) * NN + n0 + lc4];
        float4 bv = *(const float4*)&Bp[(size_t)(ck + lr) * NN + m0 + lc4];
        As[lr][lc4 + 0] = av.x; As[lr][lc4 + 1] = av.y;
        As[lr][lc4 + 2] = av.z; As[lr][lc4 + 3] = av.w;
        Bs[lr][lc4 + 0] = bv.x; Bs[lr][lc4 + 1] = bv.y;
        Bs[lr][lc4 + 2] = bv.z; Bs[lr][lc4 + 3] = bv.w;
        __syncthreads();
        #pragma unroll
        for (int k = 0; k < 8; ++k) {
            float a[8], bb[8];
            *(float4*)&a[0]  = *(const float4*)&As[k][8 * ty];
            *(float4*)&a[4]  = *(const float4*)&As[k][8 * ty + 4];
            *(float4*)&bb[0] = *(const float4*)&Bs[k][8 * tx];
            *(float4*)&bb[4] = *(const float4*)&Bs[k][8 * tx + 4];
            #pragma unroll
            for (int i = 0; i < 8; ++i)
                #pragma unroll
                for (int j = 0; j < 8; ++j)
                    acc[i][j] = fmaf(a[i], bb[j], acc[i][j]);
        }
        __syncthreads();
    }

    float* Sb = g_M + (size_t)b * NN * NN;
    #pragma unroll
    for (int i = 0; i < 8; ++i) {
        float* dst = Sb + (size_t)(n0 + 8 * ty + i) * NN + m0 + 8 * tx;
        *(float4*)dst       = make_float4(acc[i][0], acc[i][1], acc[i][2], acc[i][3]);
        *(float4*)(dst + 4) = make_float4(acc[i][4], acc[i][5], acc[i][6], acc[i][7]);
    }
}

// ---------------- kernel 3: row softmax over g_M (in place) ------------------
__global__ void softmax_kernel() {
    __shared__ float red[32];
    size_t row = blockIdx.x;
    float4* p = (float4*)(g_M + row * (size_t)NN);

    int tid  = threadIdx.x;
    int lane = tid & 31;
    int warp = tid >> 5;

    float4 v[4];
    #pragma unroll
    for (int i = 0; i < 4; ++i) v[i] = p[i * 256 + tid];

    float mx = -1e30f;
    #pragma unroll
    for (int i = 0; i < 4; ++i)
        mx = fmaxf(mx, fmaxf(fmaxf(v[i].x, v[i].y), fmaxf(v[i].z, v[i].w)));
    #pragma unroll
    for (int o = 16; o > 0; o >>= 1)
        mx = fmaxf(mx, __shfl_xor_sync(0xffffffffu, mx, o));
    if (lane == 0) red[warp] = mx;
    __syncthreads();
    if (tid < 32) {
        float m = (tid < 8) ? red[tid] : -1e30f;
        #pragma unroll
        for (int o = 4; o > 0; o >>= 1)
            m = fmaxf(m, __shfl_xor_sync(0xffffffffu, m, o));
        if (tid == 0) red[0] = m;
    }
    __syncthreads();
    mx = red[0];
    __syncthreads();

    float s = 0.0f;
    #pragma unroll
    for (int i = 0; i < 4; ++i) {
        v[i].x = __expf(v[i].x - mx);
        v[i].y = __expf(v[i].y - mx);
        v[i].z = __expf(v[i].z - mx);
        v[i].w = __expf(v[i].w - mx);
        s += v[i].x + v[i].y + v[i].z + v[i].w;
    }
    #pragma unroll
    for (int o = 16; o > 0; o >>= 1)
        s += __shfl_xor_sync(0xffffffffu, s, o);
    if (lane == 0) red[warp] = s;
    __syncthreads();
    if (tid < 32) {
        float t = (tid < 8) ? red[tid] : 0.0f;
        #pragma unroll
        for (int o = 4; o > 0; o >>= 1)
            t += __shfl_xor_sync(0xffffffffu, t, o);
        if (tid == 0) red[0] = t;
    }
    __syncthreads();
    float rs = 1.0f / red[0];

    #pragma unroll
    for (int i = 0; i < 4; ++i) {
        v[i].x *= rs; v[i].y *= rs; v[i].z *= rs; v[i].w *= rs;
        p[i * 256 + tid] = v[i];
    }
}

// ---------------- kernel 4: out[b][c][n] = alpha*sum_m M[b][n][m]*D[b][c][m] -
// NT GEMM: both operands k(=m)-contiguous -> transpose on smem store.
// 128x128 tile (c x n), BK=8, 8x8 microtile. grid (32 n, 2 c, 8 b).
__global__ void __launch_bounds__(256, 2)
gemm_out_kernel(const float* __restrict__ alpha_p,
                float* __restrict__ out) {
    int b  = blockIdx.z;
    int c0 = blockIdx.y * 128;
    int n0 = blockIdx.x * 128;

    __shared__ float Ds[8][132];   // [m_l][c_l]
    __shared__ float Ms[8][132];   // [m_l][n_l]

    int tid = threadIdx.x;
    int tx = tid & 15, ty = tid >> 4;
    int lrow = tid >> 1;           // 0..127 (c_l or n_l)
    int lh   = (tid & 1) * 4;      // 0 or 4 (which half of the 8 k-floats)

    const float* Db = g_D + (size_t)b * CC * NN;
    const float* Mb = g_M + (size_t)b * NN * NN;

    float acc[8][8] = {};
    for (int mk = 0; mk < NN; mk += 8) {
        float4 dv = *(const float4*)&Db[(size_t)(c0 + lrow) * NN + mk + lh];
        float4 mv = *(const float4*)&Mb[(size_t)(n0 + lrow) * NN + mk + lh];
        Ds[lh + 0][lrow] = dv.x; Ds[lh + 1][lrow] = dv.y;
        Ds[lh + 2][lrow] = dv.z; Ds[lh + 3][lrow] = dv.w;
        Ms[lh + 0][lrow] = mv.x; Ms[lh + 1][lrow] = mv.y;
        Ms[lh + 2][lrow] = mv.z; Ms[lh + 3][lrow] = mv.w;
        __syncthreads();
        #pragma unroll
        for (int k = 0; k < 8; ++k) {
            float d[8], m[8];
            *(float4*)&d[0] = *(const float4*)&Ds[k][8 * ty];
            *(float4*)&d[4] = *(const float4*)&Ds[k][8 * ty + 4];
            *(float4*)&m[0] = *(const float4*)&Ms[k][8 * tx];
            *(float4*)&m[4] = *(const float4*)&Ms[k][8 * tx + 4];
            #pragma unroll
            for (int i = 0; i < 8; ++i)
                #pragma unroll
                for (int j = 0; j < 8; ++j)
                    acc[i][j] = fmaf(d[i], m[j], acc[i][j]);
        }
        __syncthreads();
    }

    float alpha = *alpha_p;
    #pragma unroll
    for (int i = 0; i < 8; ++i) {
        float* dst = out + ((size_t)b * CC + c0 + 8 * ty + i) * NN + n0 + 8 * tx;
        *(float4*)dst       = make_float4(alpha * acc[i][0], alpha * acc[i][1],
                                          alpha * acc[i][2], alpha * acc[i][3]);
        *(float4*)(dst + 4) = make_float4(alpha * acc[i][4], alpha * acc[i][5],
                                          alpha * acc[i][6], alpha * acc[i][7]);
    }
}

// ---------------- launch -----------------------------------------------------
extern "C" void kernel_launch(void* const* d_in, const int* in_sizes, int n_in,
                              void* d_out, int out_size) {
    const float* X     = (const float*)d_in[0];
    const float* w1    = (const float*)d_in[1];
    const float* b1    = (const float*)d_in[2];
    const float* w2    = (const float*)d_in[3];
    const float* b2    = (const float*)d_in[4];
    const float* w3    = (const float*)d_in[5];
    const float* b3    = (const float*)d_in[6];
    const float* alpha = (const float*)d_in[7];
    float* out = (float*)d_out;

    wtrans_kernel<<<6912, 256>>>(w1, w2, w3);

    dim3 cgrid(NN / 128, CC / 128, BB);          // (32, 2, 8)
    conv3x3_kernel<<<cgrid, 256>>>(X, b1, 0);
    conv3x3_kernel<<<cgrid, 256>>>(X, b2, 1);
    conv3x3_kernel<<<cgrid, 256>>>(X, b3, 2);

    gemm_s_kernel<<<dim3(NN / 128, NN / 128, BB), 256>>>();   // (32, 32, 8)

    softmax_kernel<<<BB * NN, 256>>>();                       // 32768 rows

    gemm_out_kernel<<<dim3(NN / 128, CC / 128, BB), 256>>>(alpha, out);
}

// round 7
// speedup vs baseline: 1.6162x; 1.6162x over previous
#include <cuda_runtime.h>
#include <cuda_bf16.h>
#include <cstdint>
#include <cstddef>

// Problem: X [8,256,64,64]; three 3x3 SAME convs 256->256; spatial attention.
#define BB 8
#define CC 256
#define HH 64
#define WW 64
#define NNPIX 4096
#define KCONV 2304            // 9 taps * 256 ci

// ======================= scratch (__device__, no allocs) =====================
__device__ __align__(128) float          g_M[134217728];                 // logits fp32 [b][n][m]
__device__ __align__(128) __nv_bfloat16  g_Ph[134217728];                // probs hi  [b][n][m]
__device__ __align__(128) __nv_bfloat16  g_Pl[134217728];                // probs lo
__device__ __align__(128) __nv_bfloat16  g_Xch[75497472];                // im2col hi [b][n][k]
__device__ __align__(128) __nv_bfloat16  g_Xcl[75497472];                // im2col lo
__device__ __align__(128) __nv_bfloat16  g_Ah[8388608], g_Al[8388608];   // feat1 [b][n][c]
__device__ __align__(128) __nv_bfloat16  g_Bh[8388608], g_Bl[8388608];   // feat2 [b][n][c]
__device__ __align__(128) __nv_bfloat16  g_Dh[8388608], g_Dl[8388608];   // feat3 [b][c][n]
__device__ __align__(128) __nv_bfloat16  g_Wh[1769472], g_Wl[1769472];   // [which][co][k]

// ======================= helpers =============================================
__device__ __forceinline__ uint32_t smem_u32(const void* p) {
    uint32_t a;
    asm("{ .reg .u64 t; cvta.to.shared.u64 t, %1; cvt.u32.u64 %0, t; }"
        : "=r"(a) : "l"(p));
    return a;
}
__device__ __forceinline__ void cp16(uint32_t dst, const void* src) {
    asm volatile("cp.async.cg.shared.global [%0], [%1], 16;" :: "r"(dst), "l"(src));
}
#define CP_COMMIT() asm volatile("cp.async.commit_group;" ::: "memory")
#define CP_WAIT(n)  asm volatile("cp.async.wait_group %0;" :: "n"(n) : "memory")

__device__ __forceinline__ void ldsm_x4(uint32_t* r, uint32_t a) {
    asm volatile("ldmatrix.sync.aligned.m8n8.x4.shared.b16 {%0,%1,%2,%3}, [%4];"
        : "=r"(r[0]), "=r"(r[1]), "=r"(r[2]), "=r"(r[3]) : "r"(a));
}
__device__ __forceinline__ void ldsm_x2(uint32_t* r, uint32_t a) {
    asm volatile("ldmatrix.sync.aligned.m8n8.x2.shared.b16 {%0,%1}, [%2];"
        : "=r"(r[0]), "=r"(r[1]) : "r"(a));
}
__device__ __forceinline__ void mma_bf16(float* c, const uint32_t* a, const uint32_t* b) {
    asm volatile("mma.sync.aligned.m16n8k16.row.col.f32.bf16.bf16.f32 "
        "{%0,%1,%2,%3}, {%4,%5,%6,%7}, {%8,%9}, {%0,%1,%2,%3};"
        : "+f"(c[0]), "+f"(c[1]), "+f"(c[2]), "+f"(c[3])
        : "r"(a[0]), "r"(a[1]), "r"(a[2]), "r"(a[3]), "r"(b[0]), "r"(b[1]));
}
__device__ __forceinline__ void bsplit(float v, __nv_bfloat16& h, __nv_bfloat16& l) {
    h = __float2bfloat16(v);
    l = __float2bfloat16(v - __bfloat162float(h));
}

// ======================= prep: weights -> [which][co][tap*256+ci] hi/lo ======
__global__ void prep_weights(const float* __restrict__ w1,
                             const float* __restrict__ w2,
                             const float* __restrict__ w3) {
    int idx = blockIdx.x * 256 + threadIdx.x;      // < 3*589824
    int which = idx / 589824;
    int r     = idx % 589824;
    int co    = r / KCONV;
    int k     = r % KCONV;
    int tap   = k / 256;
    int ci    = k % 256;
    const float* w = (which == 0) ? w1 : (which == 1) ? w2 : w3;
    float v = w[(co * 256 + ci) * 9 + tap];
    bsplit(v, g_Wh[idx], g_Wl[idx]);
}

// ======================= prep: im2col hi/lo bf16 [b][n][tap*256+ci] ==========
__global__ void im2col_kernel(const float* __restrict__ X) {
    __shared__ float Xs[32][3][65];
    int y  = blockIdx.x;
    int c0 = blockIdx.y * 32;
    int b  = blockIdx.z;
    int tid = threadIdx.x;

    for (int i = tid; i < 32 * 3 * 64; i += 256) {
        int ci  = i / 192;
        int rem = i % 192;
        int r   = rem / 64;
        int x   = rem % 64;
        int yy  = y + r - 1;
        float v = 0.0f;
        if (yy >= 0 && yy < HH)
            v = X[((size_t)(b * CC + c0 + ci)) * NNPIX + yy * WW + x];
        Xs[ci][r][x] = v;
    }
    __syncthreads();

    for (int t = 0; t < 9; ++t) {
        int dy = t / 3, dx = t % 3 - 1;
        for (int i = tid; i < 2048; i += 256) {
            int ci = i & 31;
            int x  = i >> 5;
            int px = x + dx;
            float v = (px >= 0 && px < WW) ? Xs[ci][dy][px] : 0.0f;
            size_t o = ((size_t)(b * NNPIX + y * WW + x)) * KCONV + t * 256 + c0 + ci;
            bsplit(v, g_Xch[o], g_Xcl[o]);
        }
    }
}

// ======================= operand selectors ===================================
__device__ __forceinline__ const __nv_bfloat16* sel_h(int s) {
    switch (s) {
        case 0: return g_Wh;  case 1: return g_Xch; case 2: return g_Ah;
        case 3: return g_Bh;  case 4: return g_Dh;  default: return g_Ph;
    }
}
__device__ __forceinline__ const __nv_bfloat16* sel_l(int s) {
    switch (s) {
        case 0: return g_Wl;  case 1: return g_Xcl; case 2: return g_Al;
        case 3: return g_Bl;  case 4: return g_Dl;  default: return g_Pl;
    }
}
__device__ __forceinline__ __nv_bfloat16* sel_oh(int s) {
    return (s == 0) ? g_Ah : (s == 1) ? g_Bh : g_Dh;
}
__device__ __forceinline__ __nv_bfloat16* sel_ol(int s) {
    return (s == 0) ? g_Al : (s == 1) ? g_Bl : g_Dl;
}

// ======================= unified bf16 mma.sync GEMM ==========================
// D[m][n] = sum_k Aop[m][k] * Bop[n][k]  (both operands K-major), 3-pass hi/lo.
// Block tile 128x128, BK=64, 8 warps (2x4 -> 64x32 warp tiles), cp.async x2.
// MODE 0: feat epilogue  (+bias[col], bf16 hi/lo out)   conv1/conv2
// MODE 1: featD epilogue (+bias[row], bf16 hi/lo out)   conv3
// MODE 2: logits epilogue (fp32 -> g_M)
// MODE 3: final epilogue  (fp32 * alpha -> outf)
#define TILEB   18432           // 128 rows * 144B (64 bf16 + 8 pad)
#define STAGEB  (4 * TILEB)     // Ah, Al, Bh, Bl
#define GSMEM   (2 * STAGEB)    // 147456

template <int MODE>
__global__ void __launch_bounds__(256, 1)
gemm_mma(int asel, long long a_off, long a_rs, long long a_bs,
         int bsel, long long b_off, long b_rs, long long b_bs,
         int Ktot, int osel, long long o_bs, int ldo,
         float* outf, const float* __restrict__ bias)
{
    extern __shared__ char smem[];
    uint32_t sb = smem_u32(smem);
    int tid  = threadIdx.x;
    int wid  = tid >> 5, lane = tid & 31;
    int g    = lane >> 2, tig = lane & 3;
    int wm   = (wid >> 2) * 64;       // warp m-offset in block tile
    int wn   = (wid & 3) * 32;        // warp n-offset

    int bn0 = blockIdx.x * 128;
    int bm0 = blockIdx.y * 128;
    int b   = blockIdx.z;

    const __nv_bfloat16* pAh = sel_h(asel) + a_off + (size_t)b * a_bs + (size_t)bm0 * a_rs;
    const __nv_bfloat16* pAl = sel_l(asel) + a_off + (size_t)b * a_bs + (size_t)bm0 * a_rs;
    const __nv_bfloat16* pBh = sel_h(bsel) + b_off + (size_t)b * b_bs + (size_t)bn0 * b_rs;
    const __nv_bfloat16* pBl = sel_l(bsel) + b_off + (size_t)b * b_bs + (size_t)bn0 * b_rs;

    // per-thread load coords: 1024 16B-chunks per tile, 4 per thread
    float acc[4][4][4] = {};
    const int NC = Ktot >> 6;

    // ---- stage loader ----
    auto stage_load = [&](int s, int kc) {
        uint32_t base = sb + s * STAGEB;
        #pragma unroll
        for (int i = 0; i < 4; ++i) {
            int u   = tid + i * 256;
            int row = u >> 3;
            int ch  = u & 7;
            size_t ka = (size_t)row * a_rs + kc + ch * 8;
            size_t kb = (size_t)row * b_rs + kc + ch * 8;
            uint32_t d = base + row * 144 + ch * 16;
            cp16(d,              pAh + ka);
            cp16(d + TILEB,      pAl + ka);
            cp16(d + 2 * TILEB,  pBh + kb);
            cp16(d + 3 * TILEB,  pBl + kb);
        }
    };

    stage_load(0, 0);
    CP_COMMIT();

    for (int c = 0; c < NC; ++c) {
        if (c + 1 < NC) {
            stage_load((c + 1) & 1, (c + 1) * 64);
            CP_COMMIT();
            CP_WAIT(1);
        } else {
            CP_WAIT(0);
        }
        __syncthreads();

        uint32_t Ab = sb + (c & 1) * STAGEB;
        uint32_t Bb = Ab + 2 * TILEB;
        uint32_t arow = (wm + (lane & 15)) * 144 + ((lane >> 4) * 16);   // bytes
        uint32_t brow = (wn + (lane & 7)) * 144 + (((lane >> 3) & 1) * 16);

        #pragma unroll
        for (int ks = 0; ks < 4; ++ks) {
            uint32_t bh[4][2], bl[4][2];
            #pragma unroll
            for (int j = 0; j < 4; ++j) {
                uint32_t ra = Bb + brow + j * (8 * 144) + ks * 32;
                ldsm_x2(bh[j], ra);
                ldsm_x2(bl[j], ra + TILEB);
            }
            #pragma unroll
            for (int i = 0; i < 4; ++i) {
                uint32_t ah[4], al[4];
                uint32_t ra = Ab + arow + i * (16 * 144) + ks * 32;
                ldsm_x4(ah, ra);
                ldsm_x4(al, ra + TILEB);
                #pragma unroll
                for (int j = 0; j < 4; ++j) {
                    mma_bf16(acc[i][j], ah, bh[j]);   // hi*hi
                    mma_bf16(acc[i][j], ah, bl[j]);   // hi*lo
                    mma_bf16(acc[i][j], al, bh[j]);   // lo*hi
                }
            }
        }
        __syncthreads();
    }

    // ---- epilogue ----
    const float alpha = (MODE == 3) ? bias[0] : 1.0f;
    __nv_bfloat16* oh = (MODE <= 1) ? sel_oh(osel) : (__nv_bfloat16*)0;
    __nv_bfloat16* ol = (MODE <= 1) ? sel_ol(osel) : (__nv_bfloat16*)0;
    float* ofp = (MODE == 2) ? g_M : outf;
    size_t ob = (size_t)b * o_bs;

    #pragma unroll
    for (int i = 0; i < 4; ++i) {
        int row = bm0 + wm + i * 16 + g;
        float br0 = 0.0f, br1 = 0.0f;
        if (MODE == 1) { br0 = bias[row]; br1 = bias[row + 8]; }
        #pragma unroll
        for (int j = 0; j < 4; ++j) {
            int col = bn0 + wn + j * 8 + tig * 2;
            float v00 = acc[i][j][0], v01 = acc[i][j][1];
            float v10 = acc[i][j][2], v11 = acc[i][j][3];
            if (MODE == 0) {
                float bc0 = bias[col], bc1 = bias[col + 1];
                v00 += bc0; v01 += bc1; v10 += bc0; v11 += bc1;
            } else if (MODE == 1) {
                v00 += br0; v01 += br0; v10 += br1; v11 += br1;
            }
            size_t o0 = ob + (size_t)row * ldo + col;
            size_t o1 = o0 + (size_t)8 * ldo;
            if (MODE >= 2) {
                *(float2*)(ofp + o0) = make_float2(alpha * v00, alpha * v01);
                *(float2*)(ofp + o1) = make_float2(alpha * v10, alpha * v11);
            } else {
                __nv_bfloat16 h0, l0, h1, l1;
                bsplit(v00, h0, l0); bsplit(v01, h1, l1);
                *(__nv_bfloat162*)(oh + o0) = __nv_bfloat162(h0, h1);
                *(__nv_bfloat162*)(ol + o0) = __nv_bfloat162(l0, l1);
                bsplit(v10, h0, l0); bsplit(v11, h1, l1);
                *(__nv_bfloat162*)(oh + o1) = __nv_bfloat162(h0, h1);
                *(__nv_bfloat162*)(ol + o1) = __nv_bfloat162(l0, l1);
            }
        }
    }
}

// ======================= softmax: g_M row -> Ph/Pl bf16 ======================
__global__ void softmax_kernel() {
    __shared__ float red[32];
    size_t row = blockIdx.x;
    const float4* p = (const float4*)(g_M + row * (size_t)NNPIX);

    int tid  = threadIdx.x;
    int lane = tid & 31;
    int warp = tid >> 5;

    float4 v[4];
    #pragma unroll
    for (int i = 0; i < 4; ++i) v[i] = p[i * 256 + tid];

    float mx = -1e30f;
    #pragma unroll
    for (int i = 0; i < 4; ++i)
        mx = fmaxf(mx, fmaxf(fmaxf(v[i].x, v[i].y), fmaxf(v[i].z, v[i].w)));
    #pragma unroll
    for (int o = 16; o > 0; o >>= 1)
        mx = fmaxf(mx, __shfl_xor_sync(0xffffffffu, mx, o));
    if (lane == 0) red[warp] = mx;
    __syncthreads();
    if (tid < 32) {
        float m = (tid < 8) ? red[tid] : -1e30f;
        #pragma unroll
        for (int o = 4; o > 0; o >>= 1)
            m = fmaxf(m, __shfl_xor_sync(0xffffffffu, m, o));
        if (tid == 0) red[0] = m;
    }
    __syncthreads();
    mx = red[0];
    __syncthreads();

    float s = 0.0f;
    #pragma unroll
    for (int i = 0; i < 4; ++i) {
        v[i].x = __expf(v[i].x - mx);
        v[i].y = __expf(v[i].y - mx);
        v[i].z = __expf(v[i].z - mx);
        v[i].w = __expf(v[i].w - mx);
        s += v[i].x + v[i].y + v[i].z + v[i].w;
    }
    #pragma unroll
    for (int o = 16; o > 0; o >>= 1)
        s += __shfl_xor_sync(0xffffffffu, s, o);
    if (lane == 0) red[warp] = s;
    __syncthreads();
    if (tid < 32) {
        float t = (tid < 8) ? red[tid] : 0.0f;
        #pragma unroll
        for (int o = 4; o > 0; o >>= 1)
            t += __shfl_xor_sync(0xffffffffu, t, o);
        if (tid == 0) red[0] = t;
    }
    __syncthreads();
    float rs = 1.0f / red[0];

    #pragma unroll
    for (int i = 0; i < 4; ++i) {
        size_t base = row * (size_t)NNPIX + i * 1024 + tid * 4;
        float pv[4] = {v[i].x * rs, v[i].y * rs, v[i].z * rs, v[i].w * rs};
        __nv_bfloat16 h[4], l[4];
        #pragma unroll
        for (int q = 0; q < 4; ++q) bsplit(pv[q], h[q], l[q]);
        *(__nv_bfloat162*)(g_Ph + base)     = __nv_bfloat162(h[0], h[1]);
        *(__nv_bfloat162*)(g_Ph + base + 2) = __nv_bfloat162(h[2], h[3]);
        *(__nv_bfloat162*)(g_Pl + base)     = __nv_bfloat162(l[0], l[1]);
        *(__nv_bfloat162*)(g_Pl + base + 2) = __nv_bfloat162(l[2], l[3]);
    }
}

// ======================= launch ==============================================
extern "C" void kernel_launch(void* const* d_in, const int* in_sizes, int n_in,
                              void* d_out, int out_size) {
    const float* X     = (const float*)d_in[0];
    const float* w1    = (const float*)d_in[1];
    const float* b1    = (const float*)d_in[2];
    const float* w2    = (const float*)d_in[3];
    const float* b2    = (const float*)d_in[4];
    const float* w3    = (const float*)d_in[5];
    const float* b3    = (const float*)d_in[6];
    const float* alpha = (const float*)d_in[7];
    float* out = (float*)d_out;

    cudaFuncSetAttribute(gemm_mma<0>, cudaFuncAttributeMaxDynamicSharedMemorySize, GSMEM);
    cudaFuncSetAttribute(gemm_mma<1>, cudaFuncAttributeMaxDynamicSharedMemorySize, GSMEM);
    cudaFuncSetAttribute(gemm_mma<2>, cudaFuncAttributeMaxDynamicSharedMemorySize, GSMEM);
    cudaFuncSetAttribute(gemm_mma<3>, cudaFuncAttributeMaxDynamicSharedMemorySize, GSMEM);

    prep_weights<<<6912, 256>>>(w1, w2, w3);
    im2col_kernel<<<dim3(64, 8, 8), 256>>>(X);

    // conv1: M=pix (im2col rows), N=co (weight rows) -> feat1 [b][pix][co]
    gemm_mma<0><<<dim3(2, 32, 8), 256, GSMEM>>>(
        1, 0LL, KCONV, 9437184LL,     0, 0LL,       KCONV, 0LL,
        KCONV, 0, 1048576LL, 256, nullptr, b1);
    // conv2 -> feat2 [b][pix][co]
    gemm_mma<0><<<dim3(2, 32, 8), 256, GSMEM>>>(
        1, 0LL, KCONV, 9437184LL,     0, 589824LL,  KCONV, 0LL,
        KCONV, 1, 1048576LL, 256, nullptr, b2);
    // conv3: M=co, N=pix -> feat3 [b][co][pix]
    gemm_mma<1><<<dim3(32, 2, 8), 256, GSMEM>>>(
        0, 1179648LL, KCONV, 0LL,     1, 0LL,       KCONV, 9437184LL,
        KCONV, 2, 1048576LL, 4096, nullptr, b3);

    // logits: S[n][m] = sum_c feat1[n][c] * feat2[m][c]
    gemm_mma<2><<<dim3(32, 32, 8), 256, GSMEM>>>(
        2, 0LL, 256, 1048576LL,       3, 0LL,       256,   1048576LL,
        256, 0, 16777216LL, 4096, nullptr, nullptr);

    softmax_kernel<<<BB * NNPIX, 256>>>();

    // final: out[c][n] = alpha * sum_m D[c][m] * P[n][m]
    gemm_mma<3><<<dim3(32, 2, 8), 256, GSMEM>>>(
        4, 0LL, 4096, 1048576LL,      5, 0LL,       4096,  16777216LL,
        4096, 0, 1048576LL, 4096, out, alpha);
}

// round 12
// speedup vs baseline: 2.2027x; 1.3629x over previous
#include <cuda_runtime.h>
#include <cuda_bf16.h>
#include <cstdint>
#include <cstddef>

// Problem: X [8,256,64,64]; three 3x3 SAME convs 256->256; spatial attention.
#define BB 8
#define CC 256
#define HH 64
#define WW 64
#define NNPIX 4096
#define KCONV 2304            // 9 taps * 256 ci

// ======================= scratch (__device__, no allocs) =====================
__device__ __align__(128) float          g_M[134217728];                 // logits fp32 [b][n][m]
__device__ __align__(128) __nv_bfloat16  g_Ph[134217728];                // probs hi  [b][n][m]
__device__ __align__(128) __nv_bfloat16  g_Pl[134217728];                // probs lo
__device__ __align__(128) __nv_bfloat16  g_Xch[75497472];                // im2col hi [b][n][k]
__device__ __align__(128) __nv_bfloat16  g_Xcl[75497472];                // im2col lo
__device__ __align__(128) __nv_bfloat16  g_Ah[8388608], g_Al[8388608];   // feat1 [b][n][c]
__device__ __align__(128) __nv_bfloat16  g_Bh[8388608], g_Bl[8388608];   // feat2 [b][n][c]
__device__ __align__(128) __nv_bfloat16  g_Dh[8388608], g_Dl[8388608];   // feat3 [b][c][n]
__device__ __align__(128) __nv_bfloat16  g_Wh[1769472], g_Wl[1769472];   // [which][co][k]

// ======================= helpers =============================================
__device__ __forceinline__ uint32_t smem_u32(const void* p) {
    uint32_t a;
    asm("{ .reg .u64 t; cvta.to.shared.u64 t, %1; cvt.u32.u64 %0, t; }"
        : "=r"(a) : "l"(p));
    return a;
}
__device__ __forceinline__ void cp16(uint32_t dst, const void* src) {
    asm volatile("cp.async.cg.shared.global [%0], [%1], 16;" :: "r"(dst), "l"(src));
}
#define CP_COMMIT() asm volatile("cp.async.commit_group;" ::: "memory")
#define CP_WAIT(n)  asm volatile("cp.async.wait_group %0;" :: "n"(n) : "memory")

__device__ __forceinline__ void ldsm_x4(uint32_t* r, uint32_t a) {
    asm volatile("ldmatrix.sync.aligned.m8n8.x4.shared.b16 {%0,%1,%2,%3}, [%4];"
        : "=r"(r[0]), "=r"(r[1]), "=r"(r[2]), "=r"(r[3]) : "r"(a));
}
__device__ __forceinline__ void ldsm_x2(uint32_t* r, uint32_t a) {
    asm volatile("ldmatrix.sync.aligned.m8n8.x2.shared.b16 {%0,%1}, [%2];"
        : "=r"(r[0]), "=r"(r[1]) : "r"(a));
}
__device__ __forceinline__ void mma_bf16(float* c, const uint32_t* a, const uint32_t* b) {
    asm volatile("mma.sync.aligned.m16n8k16.row.col.f32.bf16.bf16.f32 "
        "{%0,%1,%2,%3}, {%4,%5,%6,%7}, {%8,%9}, {%0,%1,%2,%3};"
        : "+f"(c[0]), "+f"(c[1]), "+f"(c[2]), "+f"(c[3])
        : "r"(a[0]), "r"(a[1]), "r"(a[2]), "r"(a[3]), "r"(b[0]), "r"(b[1]));
}
__device__ __forceinline__ void bsplit(float v, __nv_bfloat16& h, __nv_bfloat16& l) {
    h = __float2bfloat16(v);
    l = __float2bfloat16(v - __bfloat162float(h));
}

// ======================= prep: weights -> [which][co][tap*256+ci] hi/lo ======
__global__ void prep_weights(const float* __restrict__ w1,
                             const float* __restrict__ w2,
                             const float* __restrict__ w3) {
    int idx = blockIdx.x * 256 + threadIdx.x;      // < 3*589824
    int which = idx / 589824;
    int r     = idx % 589824;
    int co    = r / KCONV;
    int k     = r % KCONV;
    int tap   = k / 256;
    int ci    = k % 256;
    const float* w = (which == 0) ? w1 : (which == 1) ? w2 : w3;
    float v = w[(co * 256 + ci) * 9 + tap];
    bsplit(v, g_Wh[idx], g_Wl[idx]);
}

// ======================= prep: im2col hi/lo bf16 [b][n][tap*256+ci] ==========
__global__ void im2col_kernel(const float* __restrict__ X) {
    __shared__ float Xs[32][3][65];
    int y  = blockIdx.x;
    int c0 = blockIdx.y * 32;
    int b  = blockIdx.z;
    int tid = threadIdx.x;

    for (int i = tid; i < 32 * 3 * 64; i += 256) {
        int ci  = i / 192;
        int rem = i % 192;
        int r   = rem / 64;
        int x   = rem % 64;
        int yy  = y + r - 1;
        float v = 0.0f;
        if (yy >= 0 && yy < HH)
            v = X[((size_t)(b * CC + c0 + ci)) * NNPIX + yy * WW + x];
        Xs[ci][r][x] = v;
    }
    __syncthreads();

    for (int t = 0; t < 9; ++t) {
        int dy = t / 3, dx = t % 3 - 1;
        for (int i = tid; i < 2048; i += 256) {
            int ci = i & 31;
            int x  = i >> 5;
            int px = x + dx;
            float v = (px >= 0 && px < WW) ? Xs[ci][dy][px] : 0.0f;
            size_t o = ((size_t)(b * NNPIX + y * WW + x)) * KCONV + t * 256 + c0 + ci;
            bsplit(v, g_Xch[o], g_Xcl[o]);
        }
    }
}

// ======================= operand selectors ===================================
__device__ __forceinline__ const __nv_bfloat16* sel_h(int s) {
    switch (s) {
        case 0: return g_Wh;  case 1: return g_Xch; case 2: return g_Ah;
        case 3: return g_Bh;  case 4: return g_Dh;  default: return g_Ph;
    }
}
__device__ __forceinline__ const __nv_bfloat16* sel_l(int s) {
    switch (s) {
        case 0: return g_Wl;  case 1: return g_Xcl; case 2: return g_Al;
        case 3: return g_Bl;  case 4: return g_Dl;  default: return g_Pl;
    }
}
__device__ __forceinline__ __nv_bfloat16* sel_oh(int s) {
    return (s == 0) ? g_Ah : (s == 1) ? g_Bh : g_Dh;
}
__device__ __forceinline__ __nv_bfloat16* sel_ol(int s) {
    return (s == 0) ? g_Al : (s == 1) ? g_Bl : g_Dl;
}

// ======================= unified bf16 mma.sync GEMM ==========================
// D[m][n] = sum_k Aop[m][k] * Bop[n][k]  (both operands K-major), 3-pass hi/lo.
// Block tile 128x64, BK=32, 8 warps (4x2 -> 32x32 warp tiles), cp.async x2,
// 2 CTAs/SM (smem 60KB, regs capped at 128).
// MODE 0: feat epilogue  (+bias[col], bf16 hi/lo out)   conv1/conv2
// MODE 1: featD epilogue (+bias[row], bf16 hi/lo out)   conv3
// MODE 2: logits epilogue (fp32 -> g_M)
// MODE 3: final epilogue  (fp32 * alpha -> outf)
#define TILEA   10240           // 128 rows * 80B (32 bf16 + 16B pad)
#define TILEBT  5120            // 64 rows * 80B
#define STAGEB  (2 * TILEA + 2 * TILEBT)   // 30720
#define GSMEM   (2 * STAGEB)               // 61440

template <int MODE>
__global__ void __launch_bounds__(256, 2)
gemm_mma(int asel, long long a_off, long a_rs, long long a_bs,
         int bsel, long long b_off, long b_rs, long long b_bs,
         int Ktot, int osel, long long o_bs, int ldo,
         float* outf, const float* __restrict__ bias)
{
    extern __shared__ char smem[];
    uint32_t sb = smem_u32(smem);
    int tid  = threadIdx.x;
    int wid  = tid >> 5, lane = tid & 31;
    int g    = lane >> 2, tig = lane & 3;
    int wm   = (wid >> 1) * 32;       // warp m-offset (4 rows of warps)
    int wn   = (wid & 1) * 32;        // warp n-offset (2 cols)

    int bn0 = blockIdx.x * 64;
    int bm0 = blockIdx.y * 128;
    int b   = blockIdx.z;

    const __nv_bfloat16* pAh = sel_h(asel) + a_off + (size_t)b * a_bs + (size_t)bm0 * a_rs;
    const __nv_bfloat16* pAl = sel_l(asel) + a_off + (size_t)b * a_bs + (size_t)bm0 * a_rs;
    const __nv_bfloat16* pBh = sel_h(bsel) + b_off + (size_t)b * b_bs + (size_t)bn0 * b_rs;
    const __nv_bfloat16* pBl = sel_l(bsel) + b_off + (size_t)b * b_bs + (size_t)bn0 * b_rs;

    float acc[2][4][4] = {};
    const int NC = Ktot >> 5;

    // ---- stage loader: A 2x512 chunks, B 2x256 chunks (16B each) ----
    auto stage_load = [&](int s, int kc) {
        uint32_t base = sb + s * STAGEB;
        #pragma unroll
        for (int i = 0; i < 2; ++i) {
            int u   = tid + i * 256;          // 0..511
            int row = u >> 2;
            int ch  = u & 3;
            size_t ka = (size_t)row * a_rs + kc + ch * 8;
            uint32_t d = base + row * 80 + ch * 16;
            cp16(d,         pAh + ka);
            cp16(d + TILEA, pAl + ka);
        }
        {
            int row = tid >> 2;               // 0..63
            int ch  = tid & 3;
            size_t kb = (size_t)row * b_rs + kc + ch * 8;
            uint32_t d = base + 2 * TILEA + row * 80 + ch * 16;
            cp16(d,          pBh + kb);
            cp16(d + TILEBT, pBl + kb);
        }
    };

    stage_load(0, 0);
    CP_COMMIT();

    uint32_t arow = (wm + (lane & 15)) * 80 + ((lane >> 4) * 16);
    uint32_t brow = (wn + (lane & 7)) * 80 + (((lane >> 3) & 1) * 16);

    for (int c = 0; c < NC; ++c) {
        if (c + 1 < NC) {
            stage_load((c + 1) & 1, (c + 1) * 32);
            CP_COMMIT();
            CP_WAIT(1);
        } else {
            CP_WAIT(0);
        }
        __syncthreads();

        uint32_t Ab = sb + (c & 1) * STAGEB;
        uint32_t Bb = Ab + 2 * TILEA;

        #pragma unroll
        for (int ks = 0; ks < 2; ++ks) {
            uint32_t bh[4][2], bl[4][2];
            #pragma unroll
            for (int j = 0; j < 4; ++j) {
                uint32_t ra = Bb + brow + j * (8 * 80) + ks * 32;
                ldsm_x2(bh[j], ra);
                ldsm_x2(bl[j], ra + TILEBT);
            }
            #pragma unroll
            for (int i = 0; i < 2; ++i) {
                uint32_t ah[4], al[4];
                uint32_t ra = Ab + arow + i * (16 * 80) + ks * 32;
                ldsm_x4(ah, ra);
                ldsm_x4(al, ra + TILEA);
                #pragma unroll
                for (int j = 0; j < 4; ++j) {
                    mma_bf16(acc[i][j], ah, bh[j]);   // hi*hi
                    mma_bf16(acc[i][j], ah, bl[j]);   // hi*lo
                    mma_bf16(acc[i][j], al, bh[j]);   // lo*hi
                }
            }
        }
        __syncthreads();
    }

    // ---- epilogue ----
    const float alpha = (MODE == 3) ? bias[0] : 1.0f;
    __nv_bfloat16* oh = (MODE <= 1) ? sel_oh(osel) : (__nv_bfloat16*)0;
    __nv_bfloat16* ol = (MODE <= 1) ? sel_ol(osel) : (__nv_bfloat16*)0;
    float* ofp = (MODE == 2) ? g_M : outf;
    size_t ob = (size_t)b * o_bs;

    #pragma unroll
    for (int i = 0; i < 2; ++i) {
        int row = bm0 + wm + i * 16 + g;
        float br0 = 0.0f, br1 = 0.0f;
        if (MODE == 1) { br0 = bias[row]; br1 = bias[row + 8]; }
        #pragma unroll
        for (int j = 0; j < 4; ++j) {
            int col = bn0 + wn + j * 8 + tig * 2;
            float v00 = acc[i][j][0], v01 = acc[i][j][1];
            float v10 = acc[i][j][2], v11 = acc[i][j][3];
            if (MODE == 0) {
                float bc0 = bias[col], bc1 = bias[col + 1];
                v00 += bc0; v01 += bc1; v10 += bc0; v11 += bc1;
            } else if (MODE == 1) {
                v00 += br0; v01 += br0; v10 += br1; v11 += br1;
            }
            size_t o0 = ob + (size_t)row * ldo + col;
            size_t o1 = o0 + (size_t)8 * ldo;
            if (MODE >= 2) {
                *(float2*)(ofp + o0) = make_float2(alpha * v00, alpha * v01);
                *(float2*)(ofp + o1) = make_float2(alpha * v10, alpha * v11);
            } else {
                __nv_bfloat16 h0, l0, h1, l1;
                bsplit(v00, h0, l0); bsplit(v01, h1, l1);
                *(__nv_bfloat162*)(oh + o0) = __nv_bfloat162(h0, h1);
                *(__nv_bfloat162*)(ol + o0) = __nv_bfloat162(l0, l1);
                bsplit(v10, h0, l0); bsplit(v11, h1, l1);
                *(__nv_bfloat162*)(oh + o1) = __nv_bfloat162(h0, h1);
                *(__nv_bfloat162*)(ol + o1) = __nv_bfloat162(l0, l1);
            }
        }
    }
}

// ======================= softmax: g_M row -> Ph/Pl bf16 ======================
__global__ void softmax_kernel() {
    __shared__ float red[32];
    size_t row = blockIdx.x;
    const float4* p = (const float4*)(g_M + row * (size_t)NNPIX);

    int tid  = threadIdx.x;
    int lane = tid & 31;
    int warp = tid >> 5;

    float4 v[4];
    #pragma unroll
    for (int i = 0; i < 4; ++i) v[i] = p[i * 256 + tid];

    float mx = -1e30f;
    #pragma unroll
    for (int i = 0; i < 4; ++i)
        mx = fmaxf(mx, fmaxf(fmaxf(v[i].x, v[i].y), fmaxf(v[i].z, v[i].w)));
    #pragma unroll
    for (int o = 16; o > 0; o >>= 1)
        mx = fmaxf(mx, __shfl_xor_sync(0xffffffffu, mx, o));
    if (lane == 0) red[warp] = mx;
    __syncthreads();
    if (tid < 32) {
        float m = (tid < 8) ? red[tid] : -1e30f;
        #pragma unroll
        for (int o = 4; o > 0; o >>= 1)
            m = fmaxf(m, __shfl_xor_sync(0xffffffffu, m, o));
        if (tid == 0) red[0] = m;
    }
    __syncthreads();
    mx = red[0];
    __syncthreads();

    float s = 0.0f;
    #pragma unroll
    for (int i = 0; i < 4; ++i) {
        v[i].x = __expf(v[i].x - mx);
        v[i].y = __expf(v[i].y - mx);
        v[i].z = __expf(v[i].z - mx);
        v[i].w = __expf(v[i].w - mx);
        s += v[i].x + v[i].y + v[i].z + v[i].w;
    }
    #pragma unroll
    for (int o = 16; o > 0; o >>= 1)
        s += __shfl_xor_sync(0xffffffffu, s, o);
    if (lane == 0) red[warp] = s;
    __syncthreads();
    if (tid < 32) {
        float t = (tid < 8) ? red[tid] : 0.0f;
        #pragma unroll
        for (int o = 4; o > 0; o >>= 1)
            t += __shfl_xor_sync(0xffffffffu, t, o);
        if (tid == 0) red[0] = t;
    }
    __syncthreads();
    float rs = 1.0f / red[0];

    #pragma unroll
    for (int i = 0; i < 4; ++i) {
        size_t base = row * (size_t)NNPIX + i * 1024 + tid * 4;
        float pv[4] = {v[i].x * rs, v[i].y * rs, v[i].z * rs, v[i].w * rs};
        __nv_bfloat16 h[4], l[4];
        #pragma unroll
        for (int q = 0; q < 4; ++q) bsplit(pv[q], h[q], l[q]);
        *(__nv_bfloat162*)(g_Ph + base)     = __nv_bfloat162(h[0], h[1]);
        *(__nv_bfloat162*)(g_Ph + base + 2) = __nv_bfloat162(h[2], h[3]);
        *(__nv_bfloat162*)(g_Pl + base)     = __nv_bfloat162(l[0], l[1]);
        *(__nv_bfloat162*)(g_Pl + base + 2) = __nv_bfloat162(l[2], l[3]);
    }
}

// ======================= launch ==============================================
extern "C" void kernel_launch(void* const* d_in, const int* in_sizes, int n_in,
                              void* d_out, int out_size) {
    const float* X     = (const float*)d_in[0];
    const float* w1    = (const float*)d_in[1];
    const float* b1    = (const float*)d_in[2];
    const float* w2    = (const float*)d_in[3];
    const float* b2    = (const float*)d_in[4];
    const float* w3    = (const float*)d_in[5];
    const float* b3    = (const float*)d_in[6];
    const float* alpha = (const float*)d_in[7];
    float* out = (float*)d_out;

    cudaFuncSetAttribute(gemm_mma<0>, cudaFuncAttributeMaxDynamicSharedMemorySize, GSMEM);
    cudaFuncSetAttribute(gemm_mma<1>, cudaFuncAttributeMaxDynamicSharedMemorySize, GSMEM);
    cudaFuncSetAttribute(gemm_mma<2>, cudaFuncAttributeMaxDynamicSharedMemorySize, GSMEM);
    cudaFuncSetAttribute(gemm_mma<3>, cudaFuncAttributeMaxDynamicSharedMemorySize, GSMEM);

    prep_weights<<<6912, 256>>>(w1, w2, w3);
    im2col_kernel<<<dim3(64, 8, 8), 256>>>(X);

    // conv1: M=pix (im2col rows), N=co (weight rows) -> feat1 [b][pix][co]
    gemm_mma<0><<<dim3(4, 32, 8), 256, GSMEM>>>(
        1, 0LL, KCONV, 9437184LL,     0, 0LL,       KCONV, 0LL,
        KCONV, 0, 1048576LL, 256, nullptr, b1);
    // conv2 -> feat2 [b][pix][co]
    gemm_mma<0><<<dim3(4, 32, 8), 256, GSMEM>>>(
        1, 0LL, KCONV, 9437184LL,     0, 589824LL,  KCONV, 0LL,
        KCONV, 1, 1048576LL, 256, nullptr, b2);
    // conv3: M=co, N=pix -> feat3 [b][co][pix]
    gemm_mma<1><<<dim3(64, 2, 8), 256, GSMEM>>>(
        0, 1179648LL, KCONV, 0LL,     1, 0LL,       KCONV, 9437184LL,
        KCONV, 2, 1048576LL, 4096, nullptr, b3);

    // logits: S[n][m] = sum_c feat1[n][c] * feat2[m][c]
    gemm_mma<2><<<dim3(64, 32, 8), 256, GSMEM>>>(
        2, 0LL, 256, 1048576LL,       3, 0LL,       256,   1048576LL,
        256, 0, 16777216LL, 4096, nullptr, nullptr);

    softmax_kernel<<<BB * NNPIX, 256>>>();

    // final: out[c][n] = alpha * sum_m D[c][m] * P[n][m]
    gemm_mma<3><<<dim3(64, 2, 8), 256, GSMEM>>>(
        4, 0LL, 4096, 1048576LL,      5, 0LL,       4096,  16777216LL,
        4096, 0, 1048576LL, 4096, out, alpha);
}